// round 5
// baseline (speedup 1.0000x reference)
#include <cuda_runtime.h>

#define B 8
#define L 2048
#define H 8
#define D 64
#define S 40
#define U 40
#define NBH (B*H)
#define SPLIT 8
#define CHUNK (L/SPLIT)   // 256 (K5 key chunk)
#define CHK 512           // K1 key chunk
#define NCH 4             // K1 chunk count
#define NEG_INF (-3.4e38f)

typedef unsigned long long ull;

// ---------------- f32x2 helpers ----------------
__device__ __forceinline__ ull pk2(float a, float b) {
    ull r; asm("mov.b64 %0,{%1,%2};" : "=l"(r) : "f"(a), "f"(b)); return r;
}
__device__ __forceinline__ void upk2(ull v, float& a, float& b) {
    asm("mov.b64 {%0,%1},%2;" : "=f"(a), "=f"(b) : "l"(v));
}
__device__ __forceinline__ ull fma2_(ull a, ull b, ull c) {
    ull d; asm("fma.rn.f32x2 %0,%1,%2,%3;" : "=l"(d) : "l"(a), "l"(b), "l"(c)); return d;
}
__device__ __forceinline__ ull mul2_(ull a, ull b) {
    ull d; asm("mul.rn.f32x2 %0,%1,%2;" : "=l"(d) : "l"(a), "l"(b)); return d;
}
__device__ __forceinline__ ull add2_(ull a, ull b) {
    ull d; asm("add.rn.f32x2 %0,%1,%2;" : "=l"(d) : "l"(a), "l"(b)); return d;
}

// ---------------- scratch (device globals; no allocation) ----------------
__device__ int      g_bidx[L*S];          // chunk-bucketed sample indices
__device__ unsigned g_bmeta[L*NCH];       // (off<<16)|cnt per (l,chunk)
__device__ float2   g_part[NBH*L*NCH];    // per-chunk (max, sum) partials
__device__ int      g_Mtop[NBH*U];        // top-U query indices per bh
__device__ float    g_Vpart[NBH*SPLIT*D]; // partial V sums
__device__ float    g_pO[NBH*SPLIT*U*D];  // split attention partial outputs
__device__ float    g_pm[NBH*SPLIT*U];    // split local max
__device__ float    g_pl[NBH*SPLIT*U];    // split local sum-exp

// ---------------- K0: bucket the 40 sample indices of each l by key-chunk ----------------
__global__ void __launch_bounds__(256) k0_bucket(const int* __restrict__ idxs) {
    int l = blockIdx.x * 256 + threadIdx.x;      // 2048 threads
    const int* p = idxs + l * S;
    int cnt0 = 0, cnt1 = 0, cnt2 = 0, cnt3 = 0;
    #pragma unroll
    for (int s = 0; s < S; s++) {
        int c = p[s] >> 9;
        cnt0 += (c == 0); cnt1 += (c == 1); cnt2 += (c == 2); cnt3 += (c == 3);
    }
    int o0 = 0, o1 = cnt0, o2 = o1 + cnt1, o3 = o2 + cnt2;
    g_bmeta[l*NCH + 0] = ((unsigned)o0 << 16) | (unsigned)cnt0;
    g_bmeta[l*NCH + 1] = ((unsigned)o1 << 16) | (unsigned)cnt1;
    g_bmeta[l*NCH + 2] = ((unsigned)o2 << 16) | (unsigned)cnt2;
    g_bmeta[l*NCH + 3] = ((unsigned)o3 << 16) | (unsigned)cnt3;
    int pos[4] = {o0, o1, o2, o3};
    #pragma unroll
    for (int s = 0; s < S; s++) {
        int v = p[s];
        int c = v >> 9;
        g_bidx[l*S + pos[c]] = v;
        pos[c]++;
    }
}

// ---------------- K1: chunked sampled-score partials ----------------
// block = (bh, chunk, l-half). K chunk (512x64 fp32 = 128KB) staged in smem.
// warp = 4 groups x 8 lanes; each group computes one sample dot per pass.
__device__ __forceinline__ void k1_pass(const float* __restrict__ Ks,
                                        const int* __restrict__ bp, int cnt, int base,
                                        int grp, int sub, int chbase,
                                        ull q0, ull q1, ull q2, ull q3,
                                        float& maxv, float& sumv) {
    int i = base + grp;
    bool v = i < cnt;
    int kidx = bp[v ? i : 0];
    int kr = kidx - chbase;
    const float4* kp = (const float4*)(Ks + kr*64 + sub*8);
    float4 ka = kp[0], kb = kp[1];
    ull t0 = mul2_(q0, pk2(ka.x, ka.y));
    ull t1 = mul2_(q1, pk2(ka.z, ka.w));
    t0 = fma2_(q2, pk2(kb.x, kb.y), t0);
    t1 = fma2_(q3, pk2(kb.z, kb.w), t1);
    t0 = add2_(t0, t1);
    float lo, hi; upk2(t0, lo, hi);
    float p = lo + hi;
    p += __shfl_xor_sync(0xffffffffu, p, 1);
    p += __shfl_xor_sync(0xffffffffu, p, 2);
    p += __shfl_xor_sync(0xffffffffu, p, 4);
    if (v) { maxv = fmaxf(maxv, p); sumv += p; }
}

__global__ void __launch_bounds__(512) k1_chunk(const float* __restrict__ Qg,
                                                const float* __restrict__ Kg) {
    int bh = blockIdx.x >> 3;
    int ch = (blockIdx.x >> 1) & 3;
    int lh = blockIdx.x & 1;
    int b = bh >> 3, h = bh & 7;
    int chbase = ch * CHK;
    extern __shared__ float Ks[];            // 512*64 floats
    int tid = threadIdx.x;

    // cooperative chunk load (coalesced float4)
    const float* Kbase = Kg + (size_t)(b*L + chbase)*(H*D) + h*D;
    for (int e = tid; e < CHK*D/4; e += 512) {
        int kk = e >> 4, c4 = e & 15;
        ((float4*)Ks)[kk*16 + c4] = ((const float4*)(Kbase + (size_t)kk*(H*D)))[c4];
    }
    __syncthreads();

    int lane = tid & 31, wid = tid >> 5;
    int grp = lane >> 3, sub = lane & 7;

    int l = lh*1024 + wid;
    const float* qp = Qg + ((size_t)(b*L + l)*H + h)*D + sub*8;
    float4 qa = __ldg((const float4*)qp);
    float4 qb = __ldg((const float4*)qp + 1);
    unsigned mt = g_bmeta[l*NCH + ch];

    for (int it = 0; it < 64; it++) {
        int ln  = l + 16;
        int lpf = (it == 63) ? l : ln;   // clamp prefetch on last iter
        const float* qpn = Qg + ((size_t)(b*L + lpf)*H + h)*D + sub*8;
        float4 qa_n = __ldg((const float4*)qpn);
        float4 qb_n = __ldg((const float4*)qpn + 1);
        unsigned mtn = g_bmeta[lpf*NCH + ch];

        int cnt = (int)(mt & 0xffffu);
        int off = (int)(mt >> 16);
        const int* bp = g_bidx + l*S + off;
        ull q0 = pk2(qa.x, qa.y), q1 = pk2(qa.z, qa.w);
        ull q2 = pk2(qb.x, qb.y), q3 = pk2(qb.z, qb.w);

        float maxv = NEG_INF, sumv = 0.f;
        int np = (cnt + 3) >> 2;           // uniform across warp (same l,chunk)
        int ps = 0;
        for (; ps + 2 <= np; ps += 2) {    // unroll-2: two independent chains
            k1_pass(Ks, bp, cnt, ps*4,     grp, sub, chbase, q0, q1, q2, q3, maxv, sumv);
            k1_pass(Ks, bp, cnt, ps*4 + 4, grp, sub, chbase, q0, q1, q2, q3, maxv, sumv);
        }
        if (ps < np)
            k1_pass(Ks, bp, cnt, ps*4,     grp, sub, chbase, q0, q1, q2, q3, maxv, sumv);

        // cross-group combine (uniform flow -> full-warp shuffles safe)
        maxv = fmaxf(maxv, __shfl_xor_sync(0xffffffffu, maxv, 8));
        sumv +=            __shfl_xor_sync(0xffffffffu, sumv, 8);
        maxv = fmaxf(maxv, __shfl_xor_sync(0xffffffffu, maxv, 16));
        sumv +=            __shfl_xor_sync(0xffffffffu, sumv, 16);
        if (lane == 0) g_part[(bh*L + l)*NCH + ch] = make_float2(maxv, sumv);

        qa = qa_n; qb = qb_n; mt = mtn; l = ln;
    }
}

// ---------------- K2: combine chunk partials -> M, then top-U ----------------
__global__ void __launch_bounds__(256) k2_topk() {
    __shared__ float sv[L];
    __shared__ float rv[8];
    __shared__ int   ri[8];
    int bh = blockIdx.x, tid = threadIdx.x;
    for (int i = tid; i < L; i += 256) {
        float mv = NEG_INF, sm = 0.f;
        #pragma unroll
        for (int c = 0; c < NCH; c++) {
            float2 t = g_part[(bh*L + i)*NCH + c];
            mv = fmaxf(mv, t.x);
            sm += t.y;
        }
        sv[i] = mv - sm * (1.0f / S);
    }
    __syncthreads();
    for (int it = 0; it < U; it++) {
        float v = NEG_INF; int id = 0;
        for (int i = tid; i < L; i += 256) {
            float x = sv[i];
            if (x > v) { v = x; id = i; }
        }
        for (int o = 16; o; o >>= 1) {
            float ov = __shfl_down_sync(0xffffffffu, v, o);
            int   oi = __shfl_down_sync(0xffffffffu, id, o);
            if (ov > v || (ov == v && oi < id)) { v = ov; id = oi; }
        }
        if ((tid & 31) == 0) { rv[tid >> 5] = v; ri[tid >> 5] = id; }
        __syncthreads();
        if (tid == 0) {
            float bv = rv[0]; int bi = ri[0];
            #pragma unroll
            for (int w = 1; w < 8; w++)
                if (rv[w] > bv || (rv[w] == bv && ri[w] < bi)) { bv = rv[w]; bi = ri[w]; }
            g_Mtop[bh*U + it] = bi;
            sv[bi] = NEG_INF;
        }
        __syncthreads();
    }
}

// ---------------- K3: partial V sums over L-chunks ----------------
__global__ void __launch_bounds__(256) k3_vsum(const float* __restrict__ Vg) {
    int bh = blockIdx.x >> 3, sp = blockIdx.x & 7;
    int b = bh >> 3, h = bh & 7;
    int d  = threadIdx.x & 63;
    int lg = threadIdx.x >> 6;
    const float* base = Vg + (size_t)b*L*(H*D) + h*D + d;
    int l0 = sp*CHUNK + lg;
    float a0 = 0.f, a1 = 0.f;
    #pragma unroll 8
    for (int i = 0; i < CHUNK/8; i++) {
        a0 += base[(size_t)(l0 + i*8    ) * (H*D)];
        a1 += base[(size_t)(l0 + i*8 + 4) * (H*D)];
    }
    __shared__ float red[4][64];
    red[lg][d] = a0 + a1;
    __syncthreads();
    if (threadIdx.x < 64)
        g_Vpart[(bh*SPLIT + sp)*D + threadIdx.x] =
            red[0][threadIdx.x] + red[1][threadIdx.x] + red[2][threadIdx.x] + red[3][threadIdx.x];
}

// ---------------- K4: broadcast V-mean into full output ----------------
__global__ void __launch_bounds__(256) k4_fill(float* __restrict__ out) {
    int b  = blockIdx.x >> 6;
    int r0 = (blockIdx.x & 63) * 32;
    __shared__ __align__(16) float vec[512];
    int tid = threadIdx.x;
    for (int j = tid; j < 512; j += 256) {
        int h = j >> 6, d = j & 63;
        float s = 0.f;
        #pragma unroll
        for (int sp = 0; sp < SPLIT; sp++)
            s += g_Vpart[((b*H + h)*SPLIT + sp)*D + d];
        vec[j] = s * (1.0f / L);
    }
    __syncthreads();
    float4* o4 = (float4*)(out + (size_t)(b*L + r0) * (H*D));
    const float4* v4 = (const float4*)vec;
    for (int e = tid; e < 32*128; e += 256) {
        int r = e >> 7, c = e & 127;
        o4[r*128 + c] = v4[c];
    }
}

// ---------------- K5: split-K sparse attention partials (f32x2) ----------------
// smem floats: Qs 40*64 | Ks 256*64 (float2-xor-swizzled; reused for V) | Sc 40*264
#define SCW 264
#define SM_QS 0
#define SM_KS 2560
#define SM_SC (2560 + 16384)
#define SMEM5_BYTES ((2560 + 16384 + U*SCW) * 4)

__global__ void __launch_bounds__(256) k5_attn(const float* __restrict__ Qg,
                                               const float* __restrict__ Kg,
                                               const float* __restrict__ Vg) {
    int bh = blockIdx.x >> 3, sp = blockIdx.x & 7;
    int b = bh >> 3, h = bh & 7;
    int tid = threadIdx.x;
    extern __shared__ float sm[];
    float* Qs = sm + SM_QS;
    float* Ks = sm + SM_KS;
    float* Sc = sm + SM_SC;
    float2* Qs2 = (float2*)Qs;
    float2* Ks2 = (float2*)Ks;
    __shared__ int topq[U];

    if (tid < U) topq[tid] = g_Mtop[bh*U + tid];
    __syncthreads();

    // gather selected Q rows (plain layout; float2 pairs natural)
    for (int e = tid; e < U*D; e += 256) {
        int i = e >> 6, d = e & 63;
        Qs[e] = Qg[((size_t)(b*L + topq[i])*H + h)*D + d];
    }
    // K chunk, float2-granularity swizzle: phys2 = kk*32 + (c2 ^ (kk>>3))
    const float* Kbase = Kg + (size_t)(b*L + sp*CHUNK)*(H*D) + h*D;
    for (int e = tid; e < CHUNK*D/2; e += 256) {
        int kk = e >> 5, c2 = e & 31;
        Ks2[kk*32 + (c2 ^ (kk >> 3))] = *(const float2*)(Kbase + (size_t)kk*(H*D) + c2*2);
    }
    __syncthreads();

    // phase 1: scores = Qs @ Ks^T * scale   (thread tile 5q x 8k, packed over d)
    int qg = tid >> 5, kg = tid & 31;
    ull acc2[5][8];
    ull z2 = pk2(0.f, 0.f);
    #pragma unroll
    for (int i = 0; i < 5; i++)
        #pragma unroll
        for (int j = 0; j < 8; j++) acc2[i][j] = z2;

    #pragma unroll 2
    for (int dd = 0; dd < 32; dd++) {
        ull qv[5], kv[8];
        #pragma unroll
        for (int i = 0; i < 5; i++) { float2 t = Qs2[(qg*5 + i)*32 + dd]; qv[i] = pk2(t.x, t.y); }
        #pragma unroll
        for (int j = 0; j < 8; j++) { float2 t = Ks2[(kg*8 + j)*32 + (dd ^ kg)]; kv[j] = pk2(t.x, t.y); }
        #pragma unroll
        for (int i = 0; i < 5; i++)
            #pragma unroll
            for (int j = 0; j < 8; j++) acc2[i][j] = fma2_(qv[i], kv[j], acc2[i][j]);
    }
    #pragma unroll
    for (int i = 0; i < 5; i++) {
        int q = qg*5 + i;
        float s[8];
        #pragma unroll
        for (int j = 0; j < 8; j++) { float lo, hi; upk2(acc2[i][j], lo, hi); s[j] = (lo + hi) * 0.125f; }
        float4* dst = (float4*)(Sc + q*SCW + kg*8);
        dst[0] = make_float4(s[0], s[1], s[2], s[3]);
        dst[1] = make_float4(s[4], s[5], s[6], s[7]);
    }
    __syncthreads();   // Ks reads done; Sc complete

    // load V into Ks buffer (same float2 swizzle)
    const float* Vbase = Vg + (size_t)(b*L + sp*CHUNK)*(H*D) + h*D;
    for (int e = tid; e < CHUNK*D/2; e += 256) {
        int kk = e >> 5, c2 = e & 31;
        Ks2[kk*32 + (c2 ^ (kk >> 3))] = *(const float2*)(Vbase + (size_t)kk*(H*D) + c2*2);
    }

    // per-warp local softmax on its 5 queries
    int lane = tid & 31;
    #pragma unroll
    for (int i = 0; i < 5; i++) {
        int q = qg*5 + i;
        float vals[8];
        float mv = NEG_INF;
        #pragma unroll
        for (int t = 0; t < 8; t++) {
            vals[t] = Sc[q*SCW + lane + t*32];
            mv = fmaxf(mv, vals[t]);
        }
        #pragma unroll
        for (int o = 16; o; o >>= 1) mv = fmaxf(mv, __shfl_xor_sync(0xffffffffu, mv, o));
        float ssum = 0.f;
        #pragma unroll
        for (int t = 0; t < 8; t++) {
            float ev = __expf(vals[t] - mv);
            Sc[q*SCW + lane + t*32] = ev;
            ssum += ev;
        }
        #pragma unroll
        for (int o = 16; o; o >>= 1) ssum += __shfl_xor_sync(0xffffffffu, ssum, o);
        if (lane == 0) {
            g_pm[(bh*SPLIT + sp)*U + q] = mv;
            g_pl[(bh*SPLIT + sp)*U + q] = ssum;
        }
    }
    __syncthreads();

    // phase 2: partial O = P @ V   (4 key-ranges x (5q x 8d), packed over d)
    int kr  = tid >> 6;
    int r   = tid & 63;
    int qg2 = r >> 3, dg = r & 7;
    ull facc[5][4];
    #pragma unroll
    for (int i = 0; i < 5; i++)
        #pragma unroll
        for (int j = 0; j < 4; j++) facc[i][j] = z2;

    #pragma unroll 2
    for (int kl = 0; kl < 64; kl++) {
        int kk = kr*64 + kl;
        ull pv2[5], vv[4];
        #pragma unroll
        for (int i = 0; i < 5; i++) {
            float p = Sc[(qg2*5 + i)*SCW + kk];
            pv2[i] = pk2(p, p);
        }
        int sw = kk >> 3;
        #pragma unroll
        for (int j = 0; j < 4; j++) {
            float2 t = Ks2[kk*32 + ((dg*4 + j) ^ sw)];
            vv[j] = pk2(t.x, t.y);
        }
        #pragma unroll
        for (int i = 0; i < 5; i++)
            #pragma unroll
            for (int j = 0; j < 4; j++) facc[i][j] = fma2_(pv2[i], vv[j], facc[i][j]);
    }
    __syncthreads();   // done reading Sc; reuse as reduce scratch (4*40*32 float2 = 10240 floats)
    float2* Scr = (float2*)Sc;
    #pragma unroll
    for (int i = 0; i < 5; i++) {
        int q = qg2*5 + i;
        #pragma unroll
        for (int j = 0; j < 4; j++) {
            float lo, hi; upk2(facc[i][j], lo, hi);
            Scr[kr*1280 + q*32 + dg*4 + j] = make_float2(lo, hi);
        }
    }
    __syncthreads();
    float2* pO2 = (float2*)(g_pO + (size_t)(bh*SPLIT + sp)*U*D);
    for (int e = tid; e < U*D/2; e += 256) {
        float2 a = Scr[e], b2 = Scr[1280 + e], c = Scr[2560 + e], d2 = Scr[3840 + e];
        pO2[e] = make_float2(a.x + b2.x + c.x + d2.x, a.y + b2.y + c.y + d2.y);
    }
}

// ---------------- K6: combine splits + scatter to output ----------------
__global__ void __launch_bounds__(256) k6_combine(float* __restrict__ out) {
    int bh = blockIdx.x;
    int b = bh >> 3, h = bh & 7;
    __shared__ float w[U*SPLIT];
    __shared__ int topq[U];
    int tid = threadIdx.x;
    if (tid < U) {
        topq[tid] = g_Mtop[bh*U + tid];
        float pm_[SPLIT], pl_[SPLIT];
        float m = NEG_INF;
        #pragma unroll
        for (int sp = 0; sp < SPLIT; sp++) {
            pm_[sp] = g_pm[(bh*SPLIT + sp)*U + tid];
            pl_[sp] = g_pl[(bh*SPLIT + sp)*U + tid];
            m = fmaxf(m, pm_[sp]);
        }
        float denom = 0.f, e_[SPLIT];
        #pragma unroll
        for (int sp = 0; sp < SPLIT; sp++) {
            e_[sp] = __expf(pm_[sp] - m);
            denom += pl_[sp] * e_[sp];
        }
        float inv = 1.0f / denom;
        #pragma unroll
        for (int sp = 0; sp < SPLIT; sp++) w[tid*SPLIT + sp] = e_[sp] * inv;
    }
    __syncthreads();
    for (int e = tid; e < U*D; e += 256) {
        int q = e >> 6, d = e & 63;
        float s = 0.f;
        #pragma unroll
        for (int sp = 0; sp < SPLIT; sp++)
            s += g_pO[((size_t)(bh*SPLIT + sp)*U + q)*D + d] * w[q*SPLIT + sp];
        out[((size_t)(b*L + topq[q])*H + h)*D + d] = s;
    }
}

// ---------------- launch ----------------
extern "C" void kernel_launch(void* const* d_in, const int* in_sizes, int n_in,
                              void* d_out, int out_size) {
    const float* Q   = (const float*)d_in[0];
    const float* K   = (const float*)d_in[1];
    const float* V   = (const float*)d_in[2];
    const int*  idxs = (const int*)d_in[3];
    float* out = (float*)d_out;

    cudaFuncSetAttribute(k1_chunk, cudaFuncAttributeMaxDynamicSharedMemorySize, CHK*D*4);
    cudaFuncSetAttribute(k5_attn,  cudaFuncAttributeMaxDynamicSharedMemorySize, SMEM5_BYTES);

    k0_bucket <<<L/256,        256>>>(idxs);
    k1_chunk  <<<NBH*NCH*2,    512, CHK*D*4>>>(Q, K);
    k2_topk   <<<NBH,          256>>>();
    k3_vsum   <<<NBH*SPLIT,    256>>>(V);
    k4_fill   <<<B*64,         256>>>(out);
    k5_attn   <<<NBH*SPLIT,    256, SMEM5_BYTES>>>(Q, K, V);
    k6_combine<<<NBH,          256>>>(out);
}

// round 7
// speedup vs baseline: 1.2021x; 1.2021x over previous
#include <cuda_runtime.h>

#define B 8
#define L 2048
#define H 8
#define D 64
#define S 40
#define U 40
#define NBH (B*H)
#define SPLIT 8
#define CHUNK (L/SPLIT)   // 256 (K5 key chunk)
#define K1CHK 256         // K1 key chunk rows
#define K1NCH 8           // K1 chunk count
#define NEG_INF (-3.4e38f)

typedef unsigned long long ull;

// ---------------- f32x2 helpers ----------------
__device__ __forceinline__ ull pk2(float a, float b) {
    ull r; asm("mov.b64 %0,{%1,%2};" : "=l"(r) : "f"(a), "f"(b)); return r;
}
__device__ __forceinline__ void upk2(ull v, float& a, float& b) {
    asm("mov.b64 {%0,%1},%2;" : "=f"(a), "=f"(b) : "l"(v));
}
__device__ __forceinline__ ull fma2_(ull a, ull b, ull c) {
    ull d; asm("fma.rn.f32x2 %0,%1,%2,%3;" : "=l"(d) : "l"(a), "l"(b), "l"(c)); return d;
}

// ---------------- scratch (device globals; no allocation) ----------------
__device__ int      g_cnt[L*K1NCH];       // per (l, chunk) sample count
__device__ int      g_off[L*K1NCH];       // per (l, chunk) within-chunk offset
__device__ int      g_choff[K1NCH + 1];   // chunk list offsets into g_tasks
__device__ int      g_tasks[L*S];         // compacted tasks: (l<<8)|row
__device__ float    g_pmax[NBH*L];        // atomic max of sampled scores
__device__ float    g_psum[NBH*L];        // atomic sum of sampled scores
__device__ int      g_Mtop[NBH*U];        // top-U query indices per bh
__device__ float    g_Vpart[NBH*SPLIT*D]; // partial V sums
__device__ float    g_pO[NBH*SPLIT*U*D];  // split attention partial outputs
__device__ float    g_pm[NBH*SPLIT*U];    // split local max
__device__ float    g_pl[NBH*SPLIT*U];    // split local sum-exp

// exact, order-independent float atomic max
__device__ __forceinline__ void atomicMaxF(float* addr, float v) {
    if (v >= 0.f) atomicMax((int*)addr, __float_as_int(v));
    else          atomicMin((unsigned int*)addr, __float_as_uint(v));
}

// ---------------- K0a: count samples per (l, chunk) ----------------
__global__ void __launch_bounds__(256) k0a_count(const int* __restrict__ idxs) {
    int l = blockIdx.x * 256 + threadIdx.x;
    const int* p = idxs + l * S;
    int cnt[K1NCH];
    #pragma unroll
    for (int c = 0; c < K1NCH; c++) cnt[c] = 0;
    #pragma unroll
    for (int s = 0; s < S; s++) cnt[p[s] >> 8]++;
    #pragma unroll
    for (int c = 0; c < K1NCH; c++) g_cnt[l*K1NCH + c] = cnt[c];
}

// ---------------- K0b: prefix sums (one block; warp w scans chunk w) ----------------
__global__ void __launch_bounds__(256) k0b_scan() {
    __shared__ int tot[K1NCH];
    int tid = threadIdx.x, w = tid >> 5, lane = tid & 31;
    int s = 0;
    for (int j = 0; j < 64; j++) s += g_cnt[(lane*64 + j)*K1NCH + w];
    int inc = s;
    #pragma unroll
    for (int o = 1; o < 32; o <<= 1) {
        int t = __shfl_up_sync(0xffffffffu, inc, o);
        if (lane >= o) inc += t;
    }
    int pre = inc - s;
    int run = pre;
    for (int j = 0; j < 64; j++) {
        int l = lane*64 + j;
        g_off[l*K1NCH + w] = run;
        run += g_cnt[l*K1NCH + w];
    }
    if (lane == 31) tot[w] = inc;
    __syncthreads();
    if (tid == 0) {
        int acc = 0;
        g_choff[0] = 0;
        #pragma unroll
        for (int c = 0; c < K1NCH; c++) { acc += tot[c]; g_choff[c+1] = acc; }
    }
}

// ---------------- K0c: scatter tasks (per-l thread -> deterministic order) ----------------
__global__ void __launch_bounds__(256) k0c_scatter(const int* __restrict__ idxs) {
    int l = blockIdx.x * 256 + threadIdx.x;
    const int* p = idxs + l * S;
    int pos[K1NCH];
    #pragma unroll
    for (int c = 0; c < K1NCH; c++) pos[c] = g_choff[c] + g_off[l*K1NCH + c];
    #pragma unroll
    for (int s = 0; s < S; s++) {
        int v = p[s];
        int c = v >> 8;
        g_tasks[pos[c]++] = (l << 8) | (v & 255);
    }
}

// ---------------- Kinit: reset atomic partials (graph-replay safe) ----------------
__global__ void __launch_bounds__(256) kinit_part() {
    int i = blockIdx.x * 256 + threadIdx.x;   // NBH*L threads
    g_pmax[i] = NEG_INF;
    g_psum[i] = 0.f;
}

// ---------------- K1: chunk-staged sampled dots, balanced task runs ----------------
__global__ void __launch_bounds__(256, 2) k1_dot(const float* __restrict__ Qg,
                                                 const float* __restrict__ Kg) {
    int bh = blockIdx.x >> 3, ch = blockIdx.x & 7;
    int b = bh >> 3, h = bh & 7;
    int tid = threadIdx.x, lane = tid & 31;
    extern __shared__ float Ks[];            // 256 rows x 64 floats = 64KB

    // stage K chunk (coalesced float4, plain layout)
    const float* Kbase = Kg + (size_t)(b*L + ch*K1CHK)*(H*D) + h*D;
    float4* Ks4 = (float4*)Ks;
    for (int e = tid; e < K1CHK*16; e += 256) {
        int kk = e >> 4, c4 = e & 15;
        Ks4[kk*16 + c4] = __ldg((const float4*)(Kbase + (size_t)kk*(H*D)) + c4);
    }
    __syncthreads();

    // lane-rotated chunk offsets: LDS.128 quarter-warps cover all 32 banks
    int off[16];
    #pragma unroll
    for (int t = 0; t < 16; t++) off[t] = ((t + lane) & 15) * 16;

    int base  = g_choff[ch];
    int total = g_choff[ch + 1] - base;
    int run   = (total + 255) >> 8;
    int start = tid * run;
    int end   = start + run; if (end > total) end = total;

    ull qp0[16], qp1[16];
    ull z = pk2(0.f, 0.f);
    int cur_l = -1;
    float lmax = NEG_INF, lsum = 0.f;

    for (int i = start; i < end; i++) {
        int task = g_tasks[base + i];
        int l = task >> 8;
        if (l != cur_l) {
            if (cur_l >= 0) {
                atomicMaxF(&g_pmax[bh*L + cur_l], lmax);
                atomicAdd(&g_psum[bh*L + cur_l], lsum);
            }
            cur_l = l; lmax = NEG_INF; lsum = 0.f;
            const float4* qp = (const float4*)(Qg + ((size_t)(b*L + l)*H + h)*D);
            #pragma unroll
            for (int t = 0; t < 16; t++) {
                float4 v = __ldg(qp + ((t + lane) & 15));   // rotated to match off[]
                qp0[t] = pk2(v.x, v.y);
                qp1[t] = pk2(v.z, v.w);
            }
        }
        const char* rb = (const char*)Ks + (task & 255) * 256;
        ull a0 = z, a1 = z;
        #pragma unroll
        for (int t = 0; t < 16; t++) {
            float4 kv = *(const float4*)(rb + off[t]);
            a0 = fma2_(qp0[t], pk2(kv.x, kv.y), a0);
            a1 = fma2_(qp1[t], pk2(kv.z, kv.w), a1);
        }
        float x0, x1, y0, y1; upk2(a0, x0, x1); upk2(a1, y0, y1);
        float p = (x0 + x1) + (y0 + y1);
        lmax = fmaxf(lmax, p);
        lsum += p;
    }
    if (cur_l >= 0) {
        atomicMaxF(&g_pmax[bh*L + cur_l], lmax);
        atomicAdd(&g_psum[bh*L + cur_l], lsum);
    }
}

// ---------------- K2: M = pmax - psum/S, then top-U per bh ----------------
__global__ void __launch_bounds__(256) k2_topk() {
    __shared__ float sv[L];
    __shared__ float rv[8];
    __shared__ int   ri[8];
    int bh = blockIdx.x, tid = threadIdx.x;
    for (int i = tid; i < L; i += 256)
        sv[i] = g_pmax[bh*L + i] - g_psum[bh*L + i] * (1.0f / S);
    __syncthreads();
    for (int it = 0; it < U; it++) {
        float v = NEG_INF; int id = 0;
        for (int i = tid; i < L; i += 256) {
            float x = sv[i];
            if (x > v) { v = x; id = i; }
        }
        for (int o = 16; o; o >>= 1) {
            float ov = __shfl_down_sync(0xffffffffu, v, o);
            int   oi = __shfl_down_sync(0xffffffffu, id, o);
            if (ov > v || (ov == v && oi < id)) { v = ov; id = oi; }
        }
        if ((tid & 31) == 0) { rv[tid >> 5] = v; ri[tid >> 5] = id; }
        __syncthreads();
        if (tid == 0) {
            float bv = rv[0]; int bi = ri[0];
            #pragma unroll
            for (int w = 1; w < 8; w++)
                if (rv[w] > bv || (rv[w] == bv && ri[w] < bi)) { bv = rv[w]; bi = ri[w]; }
            g_Mtop[bh*U + it] = bi;
            sv[bi] = NEG_INF;
        }
        __syncthreads();
    }
}

// ---------------- K3: partial V sums over L-chunks ----------------
__global__ void __launch_bounds__(256) k3_vsum(const float* __restrict__ Vg) {
    int bh = blockIdx.x >> 3, sp = blockIdx.x & 7;
    int b = bh >> 3, h = bh & 7;
    int d  = threadIdx.x & 63;
    int lg = threadIdx.x >> 6;
    const float* base = Vg + (size_t)b*L*(H*D) + h*D + d;
    int l0 = sp*CHUNK + lg;
    float a0 = 0.f, a1 = 0.f;
    #pragma unroll 8
    for (int i = 0; i < CHUNK/8; i++) {
        a0 += base[(size_t)(l0 + i*8    ) * (H*D)];
        a1 += base[(size_t)(l0 + i*8 + 4) * (H*D)];
    }
    __shared__ float red[4][64];
    red[lg][d] = a0 + a1;
    __syncthreads();
    if (threadIdx.x < 64)
        g_Vpart[(bh*SPLIT + sp)*D + threadIdx.x] =
            red[0][threadIdx.x] + red[1][threadIdx.x] + red[2][threadIdx.x] + red[3][threadIdx.x];
}

// ---------------- K4: broadcast V-mean into full output ----------------
__global__ void __launch_bounds__(256) k4_fill(float* __restrict__ out) {
    int b  = blockIdx.x >> 6;
    int r0 = (blockIdx.x & 63) * 32;
    __shared__ __align__(16) float vec[512];
    int tid = threadIdx.x;
    for (int j = tid; j < 512; j += 256) {
        int h = j >> 6, d = j & 63;
        float s = 0.f;
        #pragma unroll
        for (int sp = 0; sp < SPLIT; sp++)
            s += g_Vpart[((b*H + h)*SPLIT + sp)*D + d];
        vec[j] = s * (1.0f / L);
    }
    __syncthreads();
    float4* o4 = (float4*)(out + (size_t)(b*L + r0) * (H*D));
    const float4* v4 = (const float4*)vec;
    for (int e = tid; e < 32*128; e += 256) {
        int r = e >> 7, c = e & 127;
        o4[r*128 + c] = v4[c];
    }
}

// ---------------- K5: split-K sparse attention partials (round-1 proven) ----------------
#define SM_QS 0
#define SM_KS 2560
#define SM_SC (2560 + 16384)
#define SMEM5_BYTES ((2560 + 16384 + 10240) * 4)

__global__ void __launch_bounds__(256) k5_attn(const float* __restrict__ Qg,
                                               const float* __restrict__ Kg,
                                               const float* __restrict__ Vg) {
    int bh = blockIdx.x >> 3, sp = blockIdx.x & 7;
    int b = bh >> 3, h = bh & 7;
    int tid = threadIdx.x;
    extern __shared__ float sm[];
    float* Qs = sm + SM_QS;
    float* Ks = sm + SM_KS;
    float* Sc = sm + SM_SC;
    __shared__ int topq[U];

    if (tid < U) topq[tid] = g_Mtop[bh*U + tid];
    __syncthreads();

    for (int e = tid; e < U*D; e += 256) {
        int i = e >> 6, d = e & 63;
        Qs[e] = Qg[((size_t)(b*L + topq[i])*H + h)*D + d];
    }
    const float* Kbase = Kg + (size_t)(b*L + sp*CHUNK)*(H*D) + h*D;
    for (int e = tid; e < CHUNK*D; e += 256) {
        int kk = e >> 6, d = e & 63;
        Ks[kk*64 + (d ^ (kk >> 3))] = Kbase[(size_t)kk*(H*D) + d];
    }
    __syncthreads();

    int qg = tid >> 5, kg = tid & 31;
    float acc[5][8];
    #pragma unroll
    for (int i = 0; i < 5; i++)
        #pragma unroll
        for (int j = 0; j < 8; j++) acc[i][j] = 0.f;

    for (int d = 0; d < D; d++) {
        float qv[5], kv[8];
        #pragma unroll
        for (int i = 0; i < 5; i++) qv[i] = Qs[(qg*5 + i)*64 + d];
        #pragma unroll
        for (int j = 0; j < 8; j++) kv[j] = Ks[(kg*8 + j)*64 + (d ^ kg)];
        #pragma unroll
        for (int i = 0; i < 5; i++)
            #pragma unroll
            for (int j = 0; j < 8; j++) acc[i][j] = fmaf(qv[i], kv[j], acc[i][j]);
    }
    #pragma unroll
    for (int i = 0; i < 5; i++) {
        int q = qg*5 + i;
        #pragma unroll
        for (int j = 0; j < 8; j++) {
            int kk = kg*8 + j;
            Sc[q*256 + (kk ^ (q & 31))] = acc[i][j] * 0.125f;
        }
    }
    __syncthreads();

    const float* Vbase = Vg + (size_t)(b*L + sp*CHUNK)*(H*D) + h*D;
    for (int e = tid; e < CHUNK*D; e += 256) {
        int kk = e >> 6, d = e & 63;
        Ks[kk*64 + (d ^ (kk >> 3))] = Vbase[(size_t)kk*(H*D) + d];
    }

    int lane = tid & 31;
    #pragma unroll
    for (int i = 0; i < 5; i++) {
        int q = qg*5 + i;
        float vals[8];
        float mv = NEG_INF;
        #pragma unroll
        for (int t = 0; t < 8; t++) {
            int kk = lane + t*32;
            vals[t] = Sc[q*256 + (kk ^ (q & 31))];
            mv = fmaxf(mv, vals[t]);
        }
        #pragma unroll
        for (int o = 16; o; o >>= 1) mv = fmaxf(mv, __shfl_xor_sync(0xffffffffu, mv, o));
        float ssum = 0.f;
        #pragma unroll
        for (int t = 0; t < 8; t++) {
            int kk = lane + t*32;
            float ev = __expf(vals[t] - mv);
            Sc[q*256 + (kk ^ (q & 31))] = ev;
            ssum += ev;
        }
        #pragma unroll
        for (int o = 16; o; o >>= 1) ssum += __shfl_xor_sync(0xffffffffu, ssum, o);
        if (lane == 0) {
            g_pm[(bh*SPLIT + sp)*U + q] = mv;
            g_pl[(bh*SPLIT + sp)*U + q] = ssum;
        }
    }
    __syncthreads();

    int kr  = tid >> 6;
    int r   = tid & 63;
    int qg2 = r >> 3, dg = r & 7;
    float facc[5][8];
    #pragma unroll
    for (int i = 0; i < 5; i++)
        #pragma unroll
        for (int j = 0; j < 8; j++) facc[i][j] = 0.f;

    for (int kl = 0; kl < 64; kl++) {
        int kk = kr*64 + kl;
        float pv[5], vv[8];
        #pragma unroll
        for (int i = 0; i < 5; i++) {
            int q = qg2*5 + i;
            pv[i] = Sc[q*256 + (kk ^ (q & 31))];
        }
        #pragma unroll
        for (int j = 0; j < 8; j++) {
            int d = dg*8 + j;
            vv[j] = Ks[kk*64 + (d ^ (kk >> 3))];
        }
        #pragma unroll
        for (int i = 0; i < 5; i++)
            #pragma unroll
            for (int j = 0; j < 8; j++) facc[i][j] = fmaf(pv[i], vv[j], facc[i][j]);
    }
    __syncthreads();
    #pragma unroll
    for (int i = 0; i < 5; i++) {
        int q = qg2*5 + i;
        #pragma unroll
        for (int j = 0; j < 8; j++) {
            int d = dg*8 + j;
            Sc[kr*2560 + q*64 + d] = facc[i][j];
        }
    }
    __syncthreads();
    for (int e = tid; e < U*D; e += 256) {
        float s = Sc[e] + Sc[2560 + e] + Sc[5120 + e] + Sc[7680 + e];
        g_pO[(size_t)(bh*SPLIT + sp)*U*D + e] = s;
    }
}

// ---------------- K6: combine splits + scatter to output ----------------
__global__ void __launch_bounds__(256) k6_combine(float* __restrict__ out) {
    int bh = blockIdx.x;
    int b = bh >> 3, h = bh & 7;
    __shared__ float w[U*SPLIT];
    __shared__ int topq[U];
    int tid = threadIdx.x;
    if (tid < U) {
        topq[tid] = g_Mtop[bh*U + tid];
        float pm_[SPLIT], pl_[SPLIT];
        float m = NEG_INF;
        #pragma unroll
        for (int sp = 0; sp < SPLIT; sp++) {
            pm_[sp] = g_pm[(bh*SPLIT + sp)*U + tid];
            pl_[sp] = g_pl[(bh*SPLIT + sp)*U + tid];
            m = fmaxf(m, pm_[sp]);
        }
        float denom = 0.f, e_[SPLIT];
        #pragma unroll
        for (int sp = 0; sp < SPLIT; sp++) {
            e_[sp] = __expf(pm_[sp] - m);
            denom += pl_[sp] * e_[sp];
        }
        float inv = 1.0f / denom;
        #pragma unroll
        for (int sp = 0; sp < SPLIT; sp++) w[tid*SPLIT + sp] = e_[sp] * inv;
    }
    __syncthreads();
    for (int e = tid; e < U*D; e += 256) {
        int q = e >> 6, d = e & 63;
        float s = 0.f;
        #pragma unroll
        for (int sp = 0; sp < SPLIT; sp++)
            s += g_pO[((size_t)(bh*SPLIT + sp)*U + q)*D + d] * w[q*SPLIT + sp];
        out[((size_t)(b*L + topq[q])*H + h)*D + d] = s;
    }
}

// ---------------- launch ----------------
extern "C" void kernel_launch(void* const* d_in, const int* in_sizes, int n_in,
                              void* d_out, int out_size) {
    const float* Q   = (const float*)d_in[0];
    const float* K   = (const float*)d_in[1];
    const float* V   = (const float*)d_in[2];
    const int*  idxs = (const int*)d_in[3];
    float* out = (float*)d_out;

    cudaFuncSetAttribute(k1_dot,  cudaFuncAttributeMaxDynamicSharedMemorySize, K1CHK*D*4);
    cudaFuncSetAttribute(k5_attn, cudaFuncAttributeMaxDynamicSharedMemorySize, SMEM5_BYTES);

    k0a_count  <<<L/256,      256>>>(idxs);
    kinit_part <<<NBH*L/256,  256>>>();
    k0b_scan   <<<1,          256>>>();
    k0c_scatter<<<L/256,      256>>>(idxs);
    k1_dot     <<<NBH*K1NCH,  256, K1CHK*D*4>>>(Q, K);
    k2_topk    <<<NBH,        256>>>();
    k3_vsum    <<<NBH*SPLIT,  256>>>(V);
    k4_fill    <<<B*64,       256>>>(out);
    k5_attn    <<<NBH*SPLIT,  256, SMEM5_BYTES>>>(Q, K, V);
    k6_combine <<<NBH,        256>>>(out);
}